// round 1
// baseline (speedup 1.0000x reference)
#include <cuda_runtime.h>
#include <math.h>

#define NB 4
#define NN 512
#define NT 24
#define NXF 8
#define NH 64
#define NG 256     // 4*H gates
#define MROWS 2048 // B*N
#define NPRED 12

// ---- scratch (static device globals; no allocation) ----
__device__ unsigned d_mask[NN * (NN / 32)];           // 512 x 16 words
__device__ float d_Wcomb[NXF * NG];                   // 8 x 256
__device__ float d_bcomb[NG];
__device__ float d_h1[MROWS * NH], d_el1[MROWS], d_er1[MROWS], d_g1[MROWS * NH];
__device__ float d_h2[MROWS * NH], d_el2[MROWS], d_er2[MROWS], d_g2[MROWS * NH];
__device__ float d_lh[MROWS * NH];

__device__ __forceinline__ float sigf(float x) {
    return __fdividef(1.0f, 1.0f + __expf(-x));
}
__device__ __forceinline__ float tanh_f(float x) {
    return 2.0f * sigf(2.0f * x) - 1.0f;
}

// ---- mask build ----
__global__ void k_mask_zero() {
    int idx = blockIdx.x * blockDim.x + threadIdx.x;
    if (idx < NN * (NN / 32)) d_mask[idx] = 0u;
}

__global__ void k_mask_set(const int* __restrict__ ei, int E) {
    int e = blockIdx.x * blockDim.x + threadIdx.x;
    if (e < E) {
        int s = ei[e];
        int t = ei[E + e];
        atomicOr(&d_mask[s * (NN / 32) + (t >> 5)], 1u << (t & 31));
    }
}

// ---- combined LSTM input weights: Wcomb = W_fc @ W_ih^T  (8 x 256) ----
__global__ void k_wcomb(const float* __restrict__ Wfc, const float* __restrict__ bfc,
                        const float* __restrict__ Wih, const float* __restrict__ bih,
                        const float* __restrict__ bhh) {
    int j = threadIdx.x; // 0..255 gate index
    float wih[NH];
#pragma unroll
    for (int h = 0; h < NH; h++) wih[h] = Wih[j * NH + h];
#pragma unroll
    for (int f = 0; f < NXF; f++) {
        float s = 0.0f;
#pragma unroll
        for (int h = 0; h < NH; h++) s += Wfc[f * NH + h] * wih[h];
        d_Wcomb[f * NG + j] = s;
    }
    float bb = bih[j] + bhh[j];
#pragma unroll
    for (int h = 0; h < NH; h++) bb += bfc[h] * wih[h];
    d_bcomb[j] = bb;
}

// ---- GAT stage A: h = in @ W ; el = h.a_l ; er = h.a_r   (t = T-1 only) ----
// layer 0: in = x[:, :, T-1, :] @ W_fc + b_fc ;  layer 1: in = g1
__global__ void k_gatA(const float* __restrict__ x, const float* __restrict__ Wfc,
                       const float* __restrict__ bfc, const float* __restrict__ W,
                       const float* __restrict__ al, const float* __restrict__ ar,
                       int layer) {
    __shared__ float xs[NXF];
    __shared__ float in_s[NH];
    __shared__ float red[4];
    int bn = blockIdx.x;
    int i = threadIdx.x; // 0..63

    if (layer == 0) {
        if (i < NXF) xs[i] = x[bn * (NT * NXF) + (NT - 1) * NXF + i];
        __syncthreads();
        float v = bfc[i];
#pragma unroll
        for (int f = 0; f < NXF; f++) v += xs[f] * Wfc[f * NH + i];
        in_s[i] = v;
    } else {
        in_s[i] = d_g1[bn * NH + i];
    }
    __syncthreads();

    float h = 0.0f;
#pragma unroll
    for (int k = 0; k < NH; k++) h += in_s[k] * W[k * NH + i];
    (layer ? d_h2 : d_h1)[bn * NH + i] = h;

    float pl = h * al[i], pr = h * ar[i];
#pragma unroll
    for (int o = 16; o; o >>= 1) {
        pl += __shfl_xor_sync(0xffffffffu, pl, o);
        pr += __shfl_xor_sync(0xffffffffu, pr, o);
    }
    if ((i & 31) == 0) { red[(i >> 5) * 2] = pl; red[(i >> 5) * 2 + 1] = pr; }
    __syncthreads();
    if (i == 0) {
        (layer ? d_el2 : d_el1)[bn] = red[0] + red[2];
        (layer ? d_er2 : d_er1)[bn] = red[1] + red[3];
    }
}

// ---- GAT stage B: masked softmax attention + aggregate + bias + exact gelu ----
__global__ void __launch_bounds__(256) k_gatB(const float* __restrict__ bias, int layer) {
    int bm = blockIdx.x;
    int b = bm >> 9;
    int m = bm & 511;
    int tid = threadIdx.x;

    const float* hsrc = layer ? d_h2 : d_h1;
    const float* el = layer ? d_el2 : d_el1;
    const float* er = layer ? d_er2 : d_er1;
    float* gout = layer ? d_g2 : d_g1;

    __shared__ float p[NN];
    __shared__ float part[256];
    __shared__ float rbuf[8];
    __shared__ float sval[2];

    float elm = el[(b << 9) + m];

    float mx = -INFINITY;
    for (int n = tid; n < NN; n += 256) {
        float e = elm + er[(b << 9) + n];
        e = (e >= 0.0f) ? e : 0.2f * e; // leaky relu 0.2
        unsigned bit = (d_mask[(m << 4) + (n >> 5)] >> (n & 31)) & 1u;
        if (!bit) e = -INFINITY;
        p[n] = e;
        mx = fmaxf(mx, e);
    }
#pragma unroll
    for (int o = 16; o; o >>= 1) mx = fmaxf(mx, __shfl_xor_sync(0xffffffffu, mx, o));
    if ((tid & 31) == 0) rbuf[tid >> 5] = mx;
    __syncthreads();
    if (tid == 0) {
        float m2 = rbuf[0];
#pragma unroll
        for (int q = 1; q < 8; q++) m2 = fmaxf(m2, rbuf[q]);
        sval[0] = m2;
    }
    __syncthreads();
    float emax = sval[0];

    float s = 0.0f;
    for (int n = tid; n < NN; n += 256) {
        float pe = __expf(p[n] - emax);
        p[n] = pe;
        s += pe;
    }
#pragma unroll
    for (int o = 16; o; o >>= 1) s += __shfl_xor_sync(0xffffffffu, s, o);
    if ((tid & 31) == 0) rbuf[tid >> 5] = s;
    __syncthreads();
    if (tid == 0) {
        float ss = 0.0f;
#pragma unroll
        for (int q = 0; q < 8; q++) ss += rbuf[q];
        sval[1] = ss;
    }
    __syncthreads();
    float inv = __fdividef(1.0f, sval[1]);

    // aggregate: out[i] = sum_n alpha[n] * h[b,n,i], split n into 4 chunks
    int i = tid & 63;
    int ch = tid >> 6;
    const float* hb = hsrc + ((size_t)(b << 9)) * NH;
    float acc = 0.0f;
    int n0 = ch * 128;
#pragma unroll 4
    for (int n = n0; n < n0 + 128; n++) acc += p[n] * hb[n * NH + i];
    part[ch * 64 + i] = acc;
    __syncthreads();

    if (tid < 64) {
        float o_ = (part[tid] + part[64 + tid] + part[128 + tid] + part[192 + tid]) * inv
                   + bias[tid];
        float g_ = 0.5f * o_ * (1.0f + erff(o_ * 0.70710678118654752f)); // exact gelu
        gout[bm * NH + tid] = g_;
    }
}

// ---- LSTM: 8 rows per block, 24 steps internal, final h only ----
__global__ void __launch_bounds__(256) k_lstm(const float* __restrict__ x,
                                              const float* __restrict__ Whh) {
    int j = threadIdx.x;            // gate index 0..255
    int row0 = blockIdx.x * 8;

    __shared__ float Wc[NXF * NG];  // 8KB
    __shared__ float bc[NG];
    __shared__ __align__(16) float h_s[8 * NH]; // [r][k]
    __shared__ float xs[8 * NXF];
    __shared__ float gates[8 * NG]; // 8KB

#pragma unroll
    for (int f = 0; f < NXF; f++) Wc[f * NG + j] = d_Wcomb[f * NG + j];
    bc[j] = d_bcomb[j];
    for (int q = j; q < 8 * NH; q += 256) h_s[q] = 0.0f;

    float w[NH];
#pragma unroll
    for (int k = 0; k < NH; k++) w[k] = Whh[j * NH + k];

    float c0 = 0.0f, c1 = 0.0f;
    __syncthreads();

    for (int t = 0; t < NT; t++) {
        if (j < 64) {
            int r = j >> 3, f = j & 7;
            xs[j] = x[(row0 + r) * (NT * NXF) + t * NXF + f];
        }
        __syncthreads();

        float acc[8];
        float bj = bc[j];
#pragma unroll
        for (int r = 0; r < 8; r++) acc[r] = bj;
#pragma unroll
        for (int f = 0; f < NXF; f++) {
            float wf = Wc[f * NG + j];
#pragma unroll
            for (int r = 0; r < 8; r++) acc[r] += xs[r * NXF + f] * wf;
        }
#pragma unroll
        for (int k4 = 0; k4 < 16; k4++) {
#pragma unroll
            for (int r = 0; r < 8; r++) {
                float4 hv = *reinterpret_cast<const float4*>(&h_s[r * NH + k4 * 4]);
                acc[r] += hv.x * w[4 * k4] + hv.y * w[4 * k4 + 1]
                        + hv.z * w[4 * k4 + 2] + hv.w * w[4 * k4 + 3];
            }
        }
#pragma unroll
        for (int r = 0; r < 8; r++) gates[r * NG + j] = acc[r];
        __syncthreads();

        // activations: each thread owns items j and j+256
        {
            int r = j >> 6, i2 = j & 63;
            float gi = gates[r * NG + i2];
            float gf = gates[r * NG + 64 + i2];
            float gg = gates[r * NG + 128 + i2];
            float go = gates[r * NG + 192 + i2];
            float c = sigf(gf) * c0 + sigf(gi) * tanh_f(gg);
            c0 = c;
            h_s[r * NH + i2] = sigf(go) * tanh_f(c);
        }
        {
            int idx = j + 256;
            int r = idx >> 6, i2 = idx & 63;
            float gi = gates[r * NG + i2];
            float gf = gates[r * NG + 64 + i2];
            float gg = gates[r * NG + 128 + i2];
            float go = gates[r * NG + 192 + i2];
            float c = sigf(gf) * c1 + sigf(gi) * tanh_f(gg);
            c1 = c;
            h_s[r * NH + i2] = sigf(go) * tanh_f(c);
        }
        __syncthreads();
    }

    for (int q = j; q < 8 * NH; q += 256) {
        int r = q >> 6, i2 = q & 63;
        d_lh[(row0 + r) * NH + i2] = h_s[q];
    }
}

// ---- final: dual layernorm + add + decode ----
__global__ void k_final(const float* __restrict__ gl, const float* __restrict__ bl,
                        const float* __restrict__ gg, const float* __restrict__ bg,
                        const float* __restrict__ Wd, const float* __restrict__ bd,
                        float* __restrict__ out) {
    int bn = blockIdx.x;
    int i = threadIdx.x; // 0..63
    __shared__ float red[8];
    __shared__ float hs[NH];

    float vg = d_g2[bn * NH + i];
    float vl = d_lh[bn * NH + i];
    float s1 = vg, s2 = vg * vg, s3 = vl, s4 = vl * vl;
#pragma unroll
    for (int o = 16; o; o >>= 1) {
        s1 += __shfl_xor_sync(0xffffffffu, s1, o);
        s2 += __shfl_xor_sync(0xffffffffu, s2, o);
        s3 += __shfl_xor_sync(0xffffffffu, s3, o);
        s4 += __shfl_xor_sync(0xffffffffu, s4, o);
    }
    if ((i & 31) == 0) {
        int wdx = i >> 5;
        red[wdx * 4 + 0] = s1; red[wdx * 4 + 1] = s2;
        red[wdx * 4 + 2] = s3; red[wdx * 4 + 3] = s4;
    }
    __syncthreads();
    float sg = red[0] + red[4], sg2 = red[1] + red[5];
    float sl = red[2] + red[6], sl2 = red[3] + red[7];
    const float invH = 1.0f / 64.0f;
    float mug = sg * invH, varg = sg2 * invH - mug * mug;
    float mul_ = sl * invH, varl = sl2 * invH - mul_ * mul_;
    float lng = (vg - mug) * rsqrtf(varg + 1e-5f) * gg[i] + bg[i];
    float lnl = (vl - mul_) * rsqrtf(varl + 1e-5f) * gl[i] + bl[i];
    hs[i] = lng + lnl;
    __syncthreads();

    if (i < NPRED) {
        float o = bd[i];
#pragma unroll
        for (int k = 0; k < NH; k++) o += hs[k] * Wd[k * NPRED + i];
        out[bn * NPRED + i] = o;
    }
}

extern "C" void kernel_launch(void* const* d_in, const int* in_sizes, int n_in,
                              void* d_out, int out_size) {
    const float* x    = (const float*)d_in[0];
    const int*   ei   = (const int*)d_in[1];
    const float* Wfc  = (const float*)d_in[2];
    const float* bfc  = (const float*)d_in[3];
    const float* W1   = (const float*)d_in[4];
    const float* al1  = (const float*)d_in[5];
    const float* ar1  = (const float*)d_in[6];
    const float* bias1= (const float*)d_in[7];
    const float* W2   = (const float*)d_in[8];
    const float* al2  = (const float*)d_in[9];
    const float* ar2  = (const float*)d_in[10];
    const float* bias2= (const float*)d_in[11];
    const float* Wih  = (const float*)d_in[12];
    const float* Whh  = (const float*)d_in[13];
    const float* bih  = (const float*)d_in[14];
    const float* bhh  = (const float*)d_in[15];
    const float* gl   = (const float*)d_in[16];
    const float* bl   = (const float*)d_in[17];
    const float* gg   = (const float*)d_in[18];
    const float* bg   = (const float*)d_in[19];
    const float* Wd   = (const float*)d_in[20];
    const float* bd   = (const float*)d_in[21];
    float* out = (float*)d_out;

    int E = in_sizes[1] / 2;

    k_mask_zero<<<(NN * (NN / 32) + 1023) / 1024, 1024>>>();
    k_mask_set<<<(E + 255) / 256, 256>>>(ei, E);
    k_wcomb<<<1, 256>>>(Wfc, bfc, Wih, bih, bhh);

    k_gatA<<<MROWS, 64>>>(x, Wfc, bfc, W1, al1, ar1, 0);
    k_gatB<<<MROWS, 256>>>(bias1, 0);
    k_gatA<<<MROWS, 64>>>(x, Wfc, bfc, W2, al2, ar2, 1);
    k_gatB<<<MROWS, 256>>>(bias2, 1);

    k_lstm<<<MROWS / 8, 256>>>(x, Whh);

    k_final<<<MROWS, 64>>>(gl, bl, gg, bg, Wd, bd, out);
}

// round 2
// speedup vs baseline: 1.0668x; 1.0668x over previous
#include <cuda_runtime.h>
#include <math.h>

#define NN 512
#define NT 24
#define NXF 8
#define NH 64
#define NG 256
#define MROWS 2048
#define NPRED 12

// ---- scratch (static device globals; no allocation) ----
__device__ unsigned d_mask[NN * 16];
__device__ float d_Wcomb[NXF * NG];
__device__ float d_bcomb[NG];
__device__ float d_h1[MROWS * NH], d_el1[MROWS], d_er1[MROWS];
__device__ float d_h2[MROWS * NH], d_el2[MROWS], d_er2[MROWS];
__device__ float d_g2[MROWS * NH];
__device__ float d_lh[MROWS * NH];

__device__ __forceinline__ float sigf(float x) {
    return __fdividef(1.0f, 1.0f + __expf(-x));
}
__device__ __forceinline__ float tanh_f(float x) {
    return 2.0f * sigf(2.0f * x) - 1.0f;
}

__device__ __forceinline__ unsigned long long pack2(float a, float b) {
    unsigned long long r;
    asm("mov.b64 %0, {%1,%2};" : "=l"(r) : "f"(a), "f"(b));
    return r;
}
__device__ __forceinline__ void unpack2(unsigned long long v, float& a, float& b) {
    asm("mov.b64 {%0,%1}, %2;" : "=f"(a), "=f"(b) : "l"(v));
}
__device__ __forceinline__ void fma2(unsigned long long& d, unsigned long long a,
                                     unsigned long long b) {
    asm("fma.rn.f32x2 %0, %1, %2, %0;" : "+l"(d) : "l"(a), "l"(b));
}

// ---- mask build ----
__global__ void k_mask_zero() {
    int idx = blockIdx.x * blockDim.x + threadIdx.x;
    if (idx < NN * 16) d_mask[idx] = 0u;
}

__global__ void k_mask_set(const int* __restrict__ ei, int E) {
    int e = blockIdx.x * blockDim.x + threadIdx.x;
    if (e < E) {
        int s = ei[e];
        int t = ei[E + e];
        atomicOr(&d_mask[s * 16 + (t >> 5)], 1u << (t & 31));
    }
}

// ---- combined LSTM input weights: Wcomb = W_fc @ W_ih^T  (8 x 256) ----
__global__ void k_wcomb(const float* __restrict__ Wfc, const float* __restrict__ bfc,
                        const float* __restrict__ Wih, const float* __restrict__ bih,
                        const float* __restrict__ bhh) {
    int j = threadIdx.x; // 0..255 gate index
    float wih[NH];
#pragma unroll
    for (int h = 0; h < NH; h++) wih[h] = Wih[j * NH + h];
#pragma unroll
    for (int f = 0; f < NXF; f++) {
        float s = 0.0f;
#pragma unroll
        for (int h = 0; h < NH; h++) s += Wfc[f * NH + h] * wih[h];
        d_Wcomb[f * NG + j] = s;
    }
    float bb = bih[j] + bhh[j];
#pragma unroll
    for (int h = 0; h < NH; h++) bb += bfc[h] * wih[h];
    d_bcomb[j] = bb;
}

// ---- GAT layer-1 projection: 4 nodes per block, W staged in smem ----
__global__ void __launch_bounds__(256) k_gatA(const float* __restrict__ x,
                                              const float* __restrict__ Wfc,
                                              const float* __restrict__ bfc,
                                              const float* __restrict__ W,
                                              const float* __restrict__ al,
                                              const float* __restrict__ ar) {
    __shared__ float Ws[4096];
    __shared__ float wfs[512];
    __shared__ float in_s[4 * 64];
    __shared__ float xs[4 * 8];
    __shared__ float red[8][2];
    int tid = threadIdx.x;
    int bn0 = blockIdx.x * 4;
    for (int q = tid; q < 4096; q += 256) Ws[q] = W[q];
    for (int q = tid; q < 512; q += 256) wfs[q] = Wfc[q];
    if (tid < 32) xs[tid] = x[(bn0 + (tid >> 3)) * (NT * NXF) + (NT - 1) * NXF + (tid & 7)];
    __syncthreads();
    int nd = tid >> 6, i = tid & 63;
    float v = bfc[i];
#pragma unroll
    for (int f = 0; f < 8; f++) v += xs[nd * 8 + f] * wfs[f * 64 + i];
    in_s[nd * 64 + i] = v;
    __syncthreads();
    float h = 0.0f;
#pragma unroll
    for (int k = 0; k < 64; k++) h += in_s[nd * 64 + k] * Ws[k * 64 + i];
    d_h1[(bn0 + nd) * 64 + i] = h;
    float pl = h * al[i], pr = h * ar[i];
#pragma unroll
    for (int o = 16; o; o >>= 1) {
        pl += __shfl_xor_sync(0xffffffffu, pl, o);
        pr += __shfl_xor_sync(0xffffffffu, pr, o);
    }
    if ((tid & 31) == 0) { red[tid >> 5][0] = pl; red[tid >> 5][1] = pr; }
    __syncthreads();
    if ((tid & 63) == 0) {
        d_el1[bn0 + nd] = red[2 * nd][0] + red[2 * nd + 1][0];
        d_er1[bn0 + nd] = red[2 * nd][1] + red[2 * nd + 1][1];
    }
}

// ---- GAT stage B: 16 target nodes / block; softmax + f32x2 aggregate + gelu.
//      If fuse: also compute layer-2 projection h2 = g1 @ W2 and el2/er2. ----
__global__ void __launch_bounds__(256) k_gatB(const float* __restrict__ bias,
                                              const float* __restrict__ W2,
                                              const float* __restrict__ al2,
                                              const float* __restrict__ ar2,
                                              int layer) {
    __shared__ __align__(16) float p_s[9216]; // 36KB: p[512][16], later parts/gs/W2
    __shared__ float er_s[512];
    __shared__ float el_s[16];
    __shared__ float inv_s[16];
    __shared__ unsigned mask_s[256];
    __shared__ float redq[8][4][2];

    const float* hsrc = layer ? d_h2 : d_h1;
    const float* elv = layer ? d_el2 : d_el1;
    const float* erv = layer ? d_er2 : d_er1;
    int fuse = (layer == 0);

    int tid = threadIdx.x;
    int b = blockIdx.x >> 5;
    int mt = blockIdx.x & 31;
    int base = b * 512;

    for (int q = tid; q < 512; q += 256) er_s[q] = erv[base + q];
    if (tid < 16) el_s[tid] = elv[base + mt * 16 + tid];
    mask_s[tid] = d_mask[(mt * 16) * 16 + tid];
    __syncthreads();

    // -- softmax: warp w handles m = 2w, 2w+1 (16 lanes each) --
    int lane = tid & 31;
    int mloc = (tid >> 5) * 2 + (lane >> 4);
    int ll = lane & 15;
    float elm = el_s[mloc];
    float ev[32];
    float mx = -INFINITY;
#pragma unroll
    for (int q = 0; q < 32; q++) {
        int n = ll + (q << 4);
        float e = elm + er_s[n];
        e = (e >= 0.0f) ? e : 0.2f * e;
        unsigned bit = (mask_s[mloc * 16 + (q >> 1)] >> (ll + ((q & 1) << 4))) & 1u;
        e = bit ? e : -INFINITY;
        ev[q] = e;
        mx = fmaxf(mx, e);
    }
#pragma unroll
    for (int o = 8; o; o >>= 1) mx = fmaxf(mx, __shfl_xor_sync(0xffffffffu, mx, o));
    float s = 0.0f;
#pragma unroll
    for (int q = 0; q < 32; q++) {
        int n = ll + (q << 4);
        float pe = (ev[q] == -INFINITY) ? 0.0f : __expf(ev[q] - mx);
        p_s[n * 16 + mloc] = pe;
        s += pe;
    }
#pragma unroll
    for (int o = 8; o; o >>= 1) s += __shfl_xor_sync(0xffffffffu, s, o);
    if (ll == 0) inv_s[mloc] = __fdividef(1.0f, s);
    __syncthreads();

    // -- aggregate: thread (i = tid&63, quarter qd = tid>>6), 128 n each --
    const float* hb = hsrc + (size_t)base * 64;
    int i = tid & 63, qd = tid >> 6;
    unsigned long long acc[8];
#pragma unroll
    for (int j = 0; j < 8; j++) acc[j] = 0ull;
    int n0 = qd * 128;
#pragma unroll 2
    for (int n = n0; n < n0 + 128; n++) {
        float hv = hb[n * 64 + i];
        unsigned long long hd = pack2(hv, hv);
        const ulonglong2* pp = (const ulonglong2*)&p_s[n * 16];
        ulonglong2 q0 = pp[0], q1 = pp[1], q2 = pp[2], q3 = pp[3];
        fma2(acc[0], q0.x, hd); fma2(acc[1], q0.y, hd);
        fma2(acc[2], q1.x, hd); fma2(acc[3], q1.y, hd);
        fma2(acc[4], q2.x, hd); fma2(acc[5], q2.y, hd);
        fma2(acc[6], q3.x, hd); fma2(acc[7], q3.y, hd);
    }
    __syncthreads();

    // parts overlay p_s[0..4095]
    float* parts = p_s;
#pragma unroll
    for (int j = 0; j < 8; j++) {
        float a, bv;
        unpack2(acc[j], a, bv);
        parts[qd * 1024 + (2 * j) * 64 + i] = a;
        parts[qd * 1024 + (2 * j + 1) * 64 + i] = bv;
    }
    __syncthreads();

    float* gs = p_s + 4096;
#pragma unroll
    for (int oo = tid; oo < 1024; oo += 256) {
        int m = oo >> 6;
        int ii = oo & 63;
        float v = (parts[oo] + parts[1024 + oo] + parts[2048 + oo] + parts[3072 + oo])
                      * inv_s[m] + bias[ii];
        float g = 0.5f * v * (1.0f + erff(v * 0.70710678118654752f));
        if (fuse) gs[oo] = g;
        else d_g2[(size_t)(base + mt * 16) * 64 + oo] = g;
    }
    if (!fuse) return;
    __syncthreads();

    // -- fused layer-2 projection: load W2 into parts region --
    for (int q = tid; q < 4096; q += 256) p_s[q] = W2[q];
    __syncthreads();

    int g4 = tid >> 6; // reuses i = tid&63
    float h2v[4];
#pragma unroll
    for (int q2 = 0; q2 < 4; q2++) {
        int m = g4 + q2 * 4;
        float hv2 = 0.0f;
#pragma unroll
        for (int k = 0; k < 64; k++) hv2 += gs[m * 64 + k] * p_s[k * 64 + i];
        h2v[q2] = hv2;
        d_h2[(size_t)(base + mt * 16 + m) * 64 + i] = hv2;
    }
    float a_l = al2[i], a_r = ar2[i];
#pragma unroll
    for (int q2 = 0; q2 < 4; q2++) {
        float pl = h2v[q2] * a_l, pr = h2v[q2] * a_r;
#pragma unroll
        for (int o = 16; o; o >>= 1) {
            pl += __shfl_xor_sync(0xffffffffu, pl, o);
            pr += __shfl_xor_sync(0xffffffffu, pr, o);
        }
        if ((tid & 31) == 0) { redq[tid >> 5][q2][0] = pl; redq[tid >> 5][q2][1] = pr; }
    }
    __syncthreads();
    if (tid < 16) {
        int m = tid, gg = m & 3, qq = m >> 2;
        d_el2[base + mt * 16 + m] = redq[2 * gg][qq][0] + redq[2 * gg + 1][qq][0];
        d_er2[base + mt * 16 + m] = redq[2 * gg][qq][1] + redq[2 * gg + 1][qq][1];
    }
}

// ---- LSTM: 8 rows/block, packed f32x2 recurrence, final h only ----
__global__ void __launch_bounds__(256, 2) k_lstm(const float* __restrict__ x,
                                                 const float* __restrict__ Whh) {
    int j = threadIdx.x;            // gate index 0..255
    int row0 = blockIdx.x * 8;

    __shared__ __align__(16) float xs_all[8 * NT * NXF]; // 6KB  [r][t][f]
    __shared__ float gates[8 * NG];                      // 8KB
    __shared__ __align__(16) float h_s[8 * NH];          // 2KB

    for (int q = j; q < 8 * NT * NXF; q += 256) xs_all[q] = x[row0 * (NT * NXF) + q];
    for (int q = j; q < 8 * NH; q += 256) h_s[q] = 0.0f;

    unsigned long long wd[32], wcd[4];
    const float2* wr = (const float2*)(Whh + j * NH);
#pragma unroll
    for (int kk = 0; kk < 32; kk++) {
        float2 t2 = wr[kk];
        wd[kk] = pack2(t2.x, t2.y);
    }
#pragma unroll
    for (int fp = 0; fp < 4; fp++)
        wcd[fp] = pack2(d_Wcomb[(2 * fp) * NG + j], d_Wcomb[(2 * fp + 1) * NG + j]);
    float bj = d_bcomb[j];
    float c0 = 0.0f, c1 = 0.0f;
    __syncthreads();

    for (int t = 0; t < NT; t++) {
        unsigned long long acc[8];
#pragma unroll
        for (int r = 0; r < 8; r++) acc[r] = pack2(bj, 0.0f);
#pragma unroll
        for (int r = 0; r < 8; r++) {
            const unsigned long long* xp =
                (const unsigned long long*)&xs_all[r * (NT * NXF) + t * NXF];
#pragma unroll
            for (int fp = 0; fp < 4; fp++) fma2(acc[r], xp[fp], wcd[fp]);
        }
#pragma unroll
        for (int k4 = 0; k4 < 16; k4++) {
#pragma unroll
            for (int r = 0; r < 8; r++) {
                ulonglong2 hv = *(const ulonglong2*)&h_s[r * NH + k4 * 4];
                fma2(acc[r], hv.x, wd[2 * k4]);
                fma2(acc[r], hv.y, wd[2 * k4 + 1]);
            }
        }
#pragma unroll
        for (int r = 0; r < 8; r++) {
            float a, bv;
            unpack2(acc[r], a, bv);
            gates[r * NG + j] = a + bv;
        }
        __syncthreads();
        {
            int r = j >> 6, i2 = j & 63;
            float gi = gates[r * NG + i2];
            float gf = gates[r * NG + 64 + i2];
            float gg = gates[r * NG + 128 + i2];
            float go = gates[r * NG + 192 + i2];
            float c = sigf(gf) * c0 + sigf(gi) * tanh_f(gg);
            c0 = c;
            h_s[r * NH + i2] = sigf(go) * tanh_f(c);
        }
        {
            int idx = j + 256;
            int r = idx >> 6, i2 = idx & 63;
            float gi = gates[r * NG + i2];
            float gf = gates[r * NG + 64 + i2];
            float gg = gates[r * NG + 128 + i2];
            float go = gates[r * NG + 192 + i2];
            float c = sigf(gf) * c1 + sigf(gi) * tanh_f(gg);
            c1 = c;
            h_s[r * NH + i2] = sigf(go) * tanh_f(c);
        }
        __syncthreads();
    }

    for (int q = j; q < 8 * NH; q += 256) d_lh[row0 * NH + q] = h_s[q];
}

// ---- final: dual layernorm + add + decode ----
__global__ void k_final(const float* __restrict__ gl, const float* __restrict__ bl,
                        const float* __restrict__ gg, const float* __restrict__ bg,
                        const float* __restrict__ Wd, const float* __restrict__ bd,
                        float* __restrict__ out) {
    int bn = blockIdx.x;
    int i = threadIdx.x; // 0..63
    __shared__ float red[8];
    __shared__ float hs[NH];

    float vg = d_g2[bn * NH + i];
    float vl = d_lh[bn * NH + i];
    float s1 = vg, s2 = vg * vg, s3 = vl, s4 = vl * vl;
#pragma unroll
    for (int o = 16; o; o >>= 1) {
        s1 += __shfl_xor_sync(0xffffffffu, s1, o);
        s2 += __shfl_xor_sync(0xffffffffu, s2, o);
        s3 += __shfl_xor_sync(0xffffffffu, s3, o);
        s4 += __shfl_xor_sync(0xffffffffu, s4, o);
    }
    if ((i & 31) == 0) {
        int wdx = i >> 5;
        red[wdx * 4 + 0] = s1; red[wdx * 4 + 1] = s2;
        red[wdx * 4 + 2] = s3; red[wdx * 4 + 3] = s4;
    }
    __syncthreads();
    float sg = red[0] + red[4], sg2 = red[1] + red[5];
    float sl = red[2] + red[6], sl2 = red[3] + red[7];
    const float invH = 1.0f / 64.0f;
    float mug = sg * invH, varg = sg2 * invH - mug * mug;
    float mul_ = sl * invH, varl = sl2 * invH - mul_ * mul_;
    float lng = (vg - mug) * rsqrtf(varg + 1e-5f) * gg[i] + bg[i];
    float lnl = (vl - mul_) * rsqrtf(varl + 1e-5f) * gl[i] + bl[i];
    hs[i] = lng + lnl;
    __syncthreads();

    if (i < NPRED) {
        float o = bd[i];
#pragma unroll
        for (int k = 0; k < NH; k++) o += hs[k] * Wd[k * NPRED + i];
        out[bn * NPRED + i] = o;
    }
}

extern "C" void kernel_launch(void* const* d_in, const int* in_sizes, int n_in,
                              void* d_out, int out_size) {
    const float* x    = (const float*)d_in[0];
    const int*   ei   = (const int*)d_in[1];
    const float* Wfc  = (const float*)d_in[2];
    const float* bfc  = (const float*)d_in[3];
    const float* W1   = (const float*)d_in[4];
    const float* al1  = (const float*)d_in[5];
    const float* ar1  = (const float*)d_in[6];
    const float* bias1= (const float*)d_in[7];
    const float* W2   = (const float*)d_in[8];
    const float* al2  = (const float*)d_in[9];
    const float* ar2  = (const float*)d_in[10];
    const float* bias2= (const float*)d_in[11];
    const float* Wih  = (const float*)d_in[12];
    const float* Whh  = (const float*)d_in[13];
    const float* bih  = (const float*)d_in[14];
    const float* bhh  = (const float*)d_in[15];
    const float* gl   = (const float*)d_in[16];
    const float* bl   = (const float*)d_in[17];
    const float* gg   = (const float*)d_in[18];
    const float* bg   = (const float*)d_in[19];
    const float* Wd   = (const float*)d_in[20];
    const float* bd   = (const float*)d_in[21];
    float* out = (float*)d_out;

    int E = in_sizes[1] / 2;

    k_mask_zero<<<8, 1024>>>();
    k_mask_set<<<(E + 255) / 256, 256>>>(ei, E);
    k_wcomb<<<1, 256>>>(Wfc, bfc, Wih, bih, bhh);

    k_gatA<<<512, 256>>>(x, Wfc, bfc, W1, al1, ar1);
    k_gatB<<<128, 256>>>(bias1, W2, al2, ar2, 0); // fused: writes h2/el2/er2
    k_gatB<<<128, 256>>>(bias2, W2, al2, ar2, 1); // writes g2

    k_lstm<<<MROWS / 8, 256>>>(x, Whh);

    k_final<<<MROWS, 64>>>(gl, bl, gg, bg, Wd, bd, out);
}

// round 3
// speedup vs baseline: 1.4293x; 1.3398x over previous
#include <cuda_runtime.h>
#include <math.h>

#define NN 512
#define NT 24
#define NXF 8
#define NH 64
#define NG 256
#define MROWS 2048
#define NPRED 12

// ---- scratch (static device globals; no allocation) ----
__device__ float d_h1[MROWS * NH], d_el1[MROWS], d_er1[MROWS];
__device__ float d_h2[MROWS * NH], d_el2[MROWS], d_er2[MROWS];
__device__ float d_lh[MROWS * NH];
__device__ unsigned long long d_WhhP[32 * 256];   // packed pairs, [kpair][j]
__device__ unsigned long long d_WcombP[4 * 256];  // packed pairs, [fpair][j]
__device__ float d_bcomb[256];

__device__ __forceinline__ float sigf(float x) {
    return __fdividef(1.0f, 1.0f + __expf(-x));
}
__device__ __forceinline__ float tanh_f(float x) {
    return 2.0f * sigf(2.0f * x) - 1.0f;
}
__device__ __forceinline__ unsigned long long pack2(float a, float b) {
    unsigned long long r;
    asm("mov.b64 %0, {%1,%2};" : "=l"(r) : "f"(a), "f"(b));
    return r;
}
__device__ __forceinline__ void unpack2(unsigned long long v, float& a, float& b) {
    asm("mov.b64 {%0,%1}, %2;" : "=f"(a), "=f"(b) : "l"(v));
}
__device__ __forceinline__ void fma2(unsigned long long& d, unsigned long long a,
                                     unsigned long long b) {
    asm("fma.rn.f32x2 %0, %1, %2, %0;" : "+l"(d) : "l"(a), "l"(b));
}

// ---- weight prep: Wcomb = W_fc @ W_ih^T (packed), bcomb, Whh packed ----
__global__ void k_wcomb(const float* __restrict__ Wfc, const float* __restrict__ bfc,
                        const float* __restrict__ Wih, const float* __restrict__ bih,
                        const float* __restrict__ bhh, const float* __restrict__ Whh) {
    int j = threadIdx.x;
    float wih[64];
    const float4* wr = (const float4*)(Wih + j * 64);
#pragma unroll
    for (int q = 0; q < 16; q++) {
        float4 t = wr[q];
        wih[q * 4] = t.x; wih[q * 4 + 1] = t.y; wih[q * 4 + 2] = t.z; wih[q * 4 + 3] = t.w;
    }
    float wc[8];
#pragma unroll
    for (int f = 0; f < 8; f++) wc[f] = 0.0f;
    float bj = bih[j] + bhh[j];
#pragma unroll
    for (int h = 0; h < 64; h++) {
        float ww = wih[h];
        bj += bfc[h] * ww;
#pragma unroll
        for (int f = 0; f < 8; f++) wc[f] += Wfc[f * 64 + h] * ww;
    }
#pragma unroll
    for (int fp = 0; fp < 4; fp++) d_WcombP[fp * 256 + j] = pack2(wc[2 * fp], wc[2 * fp + 1]);
    d_bcomb[j] = bj;
    const float4* hr = (const float4*)(Whh + j * 64);
#pragma unroll
    for (int q = 0; q < 16; q++) {
        float4 t = hr[q];
        d_WhhP[(2 * q) * 256 + j] = pack2(t.x, t.y);
        d_WhhP[(2 * q + 1) * 256 + j] = pack2(t.z, t.w);
    }
}

// ---- GAT layer-1 projection: 16 nodes/block, 128 blocks ----
__global__ void __launch_bounds__(256) k_gatA(const float* __restrict__ x,
                                              const float* __restrict__ Wfc,
                                              const float* __restrict__ bfc,
                                              const float* __restrict__ W,
                                              const float* __restrict__ al,
                                              const float* __restrict__ ar) {
    __shared__ float Ws[4096];
    __shared__ float wfs[512];
    __shared__ float bfs[64];
    __shared__ float in_s[16 * 64];
    __shared__ float xs[16 * 8];
    __shared__ float red[8][4][2];
    int tid = threadIdx.x;
    int bn0 = blockIdx.x * 16;
    {
        const float4* src = (const float4*)W;
        float4* dst = (float4*)Ws;
        for (int q = tid; q < 1024; q += 256) dst[q] = src[q];
        const float4* s2 = (const float4*)Wfc;
        float4* d2 = (float4*)wfs;
        if (tid < 128) d2[tid] = s2[tid];
    }
    if (tid < 64) bfs[tid] = bfc[tid];
    if (tid < 128) xs[tid] = x[(bn0 + (tid >> 3)) * (NT * NXF) + (NT - 1) * NXF + (tid & 7)];
    __syncthreads();
    for (int idx = tid; idx < 1024; idx += 256) {
        int nd = idx >> 6, ii = idx & 63;
        float v = bfs[ii];
#pragma unroll
        for (int f = 0; f < 8; f++) v += xs[nd * 8 + f] * wfs[f * 64 + ii];
        in_s[idx] = v;
    }
    __syncthreads();
    int i = tid & 63, grp = tid >> 6;
    float wcol[64];
#pragma unroll
    for (int k = 0; k < 64; k++) wcol[k] = Ws[k * 64 + i];
    float a_l = al[i], a_r = ar[i];
    float pl[4], pr[4];
#pragma unroll
    for (int q = 0; q < 4; q++) {
        int nd = grp * 4 + q;
        float h = 0.0f;
#pragma unroll
        for (int k = 0; k < 64; k++) h += in_s[nd * 64 + k] * wcol[k];
        d_h1[(size_t)(bn0 + nd) * 64 + i] = h;
        pl[q] = h * a_l; pr[q] = h * a_r;
    }
#pragma unroll
    for (int q = 0; q < 4; q++) {
#pragma unroll
        for (int o = 16; o; o >>= 1) {
            pl[q] += __shfl_xor_sync(~0u, pl[q], o);
            pr[q] += __shfl_xor_sync(~0u, pr[q], o);
        }
    }
    int wp = tid >> 5, lane = tid & 31;
    if (lane == 0) {
#pragma unroll
        for (int q = 0; q < 4; q++) { red[wp][q][0] = pl[q]; red[wp][q][1] = pr[q]; }
    }
    __syncthreads();
    if (tid < 32) {
        int nd = tid >> 1, v = tid & 1;
        int g = nd >> 2, q = nd & 3;
        float s = red[2 * g][q][v] + red[2 * g + 1][q][v];
        if (v) d_er1[bn0 + nd] = s;
        else d_el1[bn0 + nd] = s;
    }
}

// ---- LSTM: 8 rows/block, packed f32x2 recurrence, coalesced packed weights ----
__global__ void __launch_bounds__(256, 2) k_lstm(const float* __restrict__ x) {
    int j = threadIdx.x;
    int row0 = blockIdx.x * 8;
    __shared__ __align__(16) float xs_all[8 * 192];
    __shared__ float gates[8 * 256];
    __shared__ __align__(16) float h_s[8 * 64];
    {
        const float4* src = (const float4*)(x + (size_t)row0 * 192);
        float4* dst = (float4*)xs_all;
        for (int q = j; q < 384; q += 256) dst[q] = src[q];
    }
    for (int q = j; q < 512; q += 256) h_s[q] = 0.0f;
    unsigned long long wd[32];
#pragma unroll
    for (int kk = 0; kk < 32; kk++) wd[kk] = d_WhhP[kk * 256 + j]; // coalesced
    unsigned long long wcd[4];
#pragma unroll
    for (int fp = 0; fp < 4; fp++) wcd[fp] = d_WcombP[fp * 256 + j];
    float bj = d_bcomb[j];
    float c0 = 0.0f, c1 = 0.0f;
    __syncthreads();

    for (int t = 0; t < NT; t++) {
        unsigned long long acc[8];
#pragma unroll
        for (int r = 0; r < 8; r++) acc[r] = pack2(bj, 0.0f);
#pragma unroll
        for (int r = 0; r < 8; r++) {
            const unsigned long long* xp =
                (const unsigned long long*)&xs_all[r * 192 + t * 8];
#pragma unroll
            for (int fp = 0; fp < 4; fp++) fma2(acc[r], xp[fp], wcd[fp]);
        }
#pragma unroll
        for (int k4 = 0; k4 < 16; k4++) {
#pragma unroll
            for (int r = 0; r < 8; r++) {
                ulonglong2 hv = *(const ulonglong2*)&h_s[r * 64 + k4 * 4];
                fma2(acc[r], hv.x, wd[2 * k4]);
                fma2(acc[r], hv.y, wd[2 * k4 + 1]);
            }
        }
#pragma unroll
        for (int r = 0; r < 8; r++) {
            float a, bv;
            unpack2(acc[r], a, bv);
            gates[r * 256 + j] = a + bv;
        }
        __syncthreads();
        {
            int r = j >> 6, i2 = j & 63;
            float gi = gates[r * 256 + i2];
            float gf = gates[r * 256 + 64 + i2];
            float gG = gates[r * 256 + 128 + i2];
            float go = gates[r * 256 + 192 + i2];
            float c = sigf(gf) * c0 + sigf(gi) * tanh_f(gG);
            c0 = c;
            h_s[r * 64 + i2] = sigf(go) * tanh_f(c);
        }
        {
            int idx = j + 256;
            int r = idx >> 6, i2 = idx & 63;
            float gi = gates[r * 256 + i2];
            float gf = gates[r * 256 + 64 + i2];
            float gG = gates[r * 256 + 128 + i2];
            float go = gates[r * 256 + 192 + i2];
            float c = sigf(gf) * c1 + sigf(gi) * tanh_f(gG);
            c1 = c;
            h_s[r * 64 + i2] = sigf(go) * tanh_f(c);
        }
        __syncthreads();
    }
    for (int q = j; q < 512; q += 256) d_lh[(size_t)row0 * 64 + q] = h_s[q];
}

// ---- GAT stage B: 16 targets/block, 512 threads, conflict-free softmax,
//      fused layer-2 projection (layer 0) or fused LN+decode (layer 1) ----
__global__ void __launch_bounds__(512) k_gatB(
    const int* __restrict__ ei, int E, const float* __restrict__ bias,
    const float* __restrict__ W2, const float* __restrict__ al2,
    const float* __restrict__ ar2, const float* __restrict__ gl,
    const float* __restrict__ bl, const float* __restrict__ gg,
    const float* __restrict__ bg, const float* __restrict__ Wd,
    const float* __restrict__ bd, float* __restrict__ out, int layer) {
    __shared__ __align__(16) float p_s[8192];  // p[n][16] -> parts -> (W2 | lh/Wd)
    __shared__ float gs[1024];
    __shared__ float er_s[512];   // reused as sum partials
    __shared__ float el_s[16];    // reused as per-m max
    __shared__ float inv_s[16];
    __shared__ unsigned mask_s[256];
    __shared__ float wred[256];
    __shared__ float red0[16][4];

    int tid = threadIdx.x;
    int b = blockIdx.x >> 5, mt = blockIdx.x & 31;
    int base = b * 512, m0 = mt * 16;

    const float* elv = layer ? d_el2 : d_el1;
    const float* erv = layer ? d_er2 : d_er1;
    const float* hsrc = layer ? d_h2 : d_h1;

    if (tid < 256) mask_s[tid] = 0u;
    er_s[tid] = erv[base + tid];
    if (tid < 16) el_s[tid] = elv[base + m0 + tid];
    __syncthreads();
    for (int e = tid; e < E; e += 512) {
        int s = ei[e];
        if ((unsigned)(s - m0) < 16u) {
            int t = ei[E + e];
            atomicOr(&mask_s[(s - m0) * 16 + (t >> 5)], 1u << (t & 31));
        }
    }
    __syncthreads();

    int lane = tid & 31, w = tid >> 5;
    // phase 1: raw e values (conflict-free stores), per-(warp,m) max
    {
        int m = lane & 15, half = lane >> 4;
        float elm = el_s[m];
        float mxp = -INFINITY;
#pragma unroll
        for (int k = 0; k < 16; k++) {
            int n = w * 32 + half * 16 + k;
            float e = elm + er_s[n];
            e = (e >= 0.0f) ? e : 0.2f * e;
            unsigned bit = (mask_s[m * 16 + (n >> 5)] >> (n & 31)) & 1u;
            e = bit ? e : -INFINITY;
            p_s[n * 16 + m] = e;
            mxp = fmaxf(mxp, e);
        }
        mxp = fmaxf(mxp, __shfl_xor_sync(~0u, mxp, 16));
        if (lane < 16) wred[w * 16 + lane] = mxp;
    }
    __syncthreads();
    if (tid < 16) {
        float mm = wred[tid];
#pragma unroll
        for (int q = 1; q < 16; q++) mm = fmaxf(mm, wred[q * 16 + tid]);
        el_s[tid] = mm;
    }
    __syncthreads();
    // phase 2: exp + per-m sum
    {
        int m2 = tid & 15, nb = tid >> 4;
        float mxm = el_s[m2];
        float sp = 0.0f;
#pragma unroll
        for (int q = 0; q < 16; q++) {
            int idx = (nb + q * 32) * 16 + m2;
            float pe = __expf(p_s[idx] - mxm);
            p_s[idx] = pe;
            sp += pe;
        }
        er_s[tid] = sp;
    }
    __syncthreads();
    if (tid < 16) {
        float s = 0.0f;
#pragma unroll
        for (int k = 0; k < 32; k++) s += er_s[k * 16 + tid];
        inv_s[tid] = __fdividef(1.0f, s);
    }
    __syncthreads();

    // aggregate: thread (i=tid&63, ch=tid>>6), 64 n each, f32x2 over 16 m
    int i = tid & 63, ch = tid >> 6;
    unsigned long long acc[8];
#pragma unroll
    for (int q = 0; q < 8; q++) acc[q] = 0ull;
    const float* hb = hsrc + (size_t)base * 64;
    {
        int n0 = ch * 64;
#pragma unroll 8
        for (int nn = 0; nn < 64; nn++) {
            int n = n0 + nn;
            float hv = hb[n * 64 + i];
            unsigned long long hd = pack2(hv, hv);
            const ulonglong2* pp = (const ulonglong2*)&p_s[n * 16];
            ulonglong2 q0 = pp[0], q1 = pp[1], q2 = pp[2], q3 = pp[3];
            fma2(acc[0], q0.x, hd); fma2(acc[1], q0.y, hd);
            fma2(acc[2], q1.x, hd); fma2(acc[3], q1.y, hd);
            fma2(acc[4], q2.x, hd); fma2(acc[5], q2.y, hd);
            fma2(acc[6], q3.x, hd); fma2(acc[7], q3.y, hd);
        }
    }
    __syncthreads();
#pragma unroll
    for (int q = 0; q < 8; q++) {
        float a, bv;
        unpack2(acc[q], a, bv);
        p_s[ch * 1024 + (2 * q) * 64 + i] = a;
        p_s[ch * 1024 + (2 * q + 1) * 64 + i] = bv;
    }
    __syncthreads();
    for (int oo = tid; oo < 1024; oo += 512) {
        float v = 0.0f;
#pragma unroll
        for (int q2 = 0; q2 < 8; q2++) v += p_s[q2 * 1024 + oo];
        v = v * inv_s[oo >> 6] + bias[oo & 63];
        gs[oo] = 0.5f * v * (1.0f + erff(v * 0.70710678118654752f));
    }
    __syncthreads();

    if (layer == 0) {
        // fused layer-2 projection: h2 = gs @ W2, el2/er2
        for (int q = tid; q < 4096; q += 512) p_s[q] = W2[q];
        __syncthreads();
        int g = tid >> 6;
        float h2a = 0.0f, h2b = 0.0f;
#pragma unroll
        for (int k = 0; k < 64; k++) {
            float wv = p_s[k * 64 + i];
            h2a += gs[g * 64 + k] * wv;
            h2b += gs[(g + 8) * 64 + k] * wv;
        }
        d_h2[(size_t)(base + m0 + g) * 64 + i] = h2a;
        d_h2[(size_t)(base + m0 + g + 8) * 64 + i] = h2b;
        float a_l = al2[i], a_r = ar2[i];
        float pla = h2a * a_l, pra = h2a * a_r, plb = h2b * a_l, prb = h2b * a_r;
#pragma unroll
        for (int o = 16; o; o >>= 1) {
            pla += __shfl_xor_sync(~0u, pla, o);
            pra += __shfl_xor_sync(~0u, pra, o);
            plb += __shfl_xor_sync(~0u, plb, o);
            prb += __shfl_xor_sync(~0u, prb, o);
        }
        if (lane == 0) {
            red0[w][0] = pla; red0[w][1] = pra; red0[w][2] = plb; red0[w][3] = prb;
        }
        __syncthreads();
        if (tid < 32) {
            int m = tid >> 1, v = tid & 1;
            int g2 = m & 7, hi = m >> 3;
            float s = red0[2 * g2][hi * 2 + v] + red0[2 * g2 + 1][hi * 2 + v];
            if (v) d_er2[base + m0 + m] = s;
            else d_el2[base + m0 + m] = s;
        }
    } else {
        // fused final: dual layernorm + add + decode; warp w handles node m=w
        float* lh_s = p_s;
        float* Wds = p_s + 1024;
        for (int q = tid; q < 1024; q += 512) lh_s[q] = d_lh[(size_t)(base + m0) * 64 + q];
        for (int q = tid; q < 768; q += 512) Wds[q] = Wd[q];
        __syncthreads();
        int ia = lane, ib = lane + 32;
        float vg0 = gs[w * 64 + ia], vg1 = gs[w * 64 + ib];
        float vl0 = lh_s[w * 64 + ia], vl1 = lh_s[w * 64 + ib];
        float s1 = vg0 + vg1, s2 = vg0 * vg0 + vg1 * vg1;
        float s3 = vl0 + vl1, s4 = vl0 * vl0 + vl1 * vl1;
#pragma unroll
        for (int o = 16; o; o >>= 1) {
            s1 += __shfl_xor_sync(~0u, s1, o);
            s2 += __shfl_xor_sync(~0u, s2, o);
            s3 += __shfl_xor_sync(~0u, s3, o);
            s4 += __shfl_xor_sync(~0u, s4, o);
        }
        const float invH = 1.0f / 64.0f;
        float mug = s1 * invH, varg = s2 * invH - mug * mug;
        float mul_ = s3 * invH, varl = s4 * invH - mul_ * mul_;
        float rg = rsqrtf(varg + 1e-5f), rl = rsqrtf(varl + 1e-5f);
        float h0 = (vg0 - mug) * rg * gg[ia] + bg[ia] + (vl0 - mul_) * rl * gl[ia] + bl[ia];
        float h1v = (vg1 - mug) * rg * gg[ib] + bg[ib] + (vl1 - mul_) * rl * gl[ib] + bl[ib];
        __syncwarp();
        lh_s[w * 64 + ia] = h0;
        lh_s[w * 64 + ib] = h1v;
        __syncwarp();
        if (lane < NPRED) {
            float o = bd[lane];
#pragma unroll
            for (int k = 0; k < 64; k++) o += lh_s[w * 64 + k] * Wds[k * NPRED + lane];
            out[(size_t)(base + m0 + w) * NPRED + lane] = o;
        }
    }
}

extern "C" void kernel_launch(void* const* d_in, const int* in_sizes, int n_in,
                              void* d_out, int out_size) {
    const float* x    = (const float*)d_in[0];
    const int*   ei   = (const int*)d_in[1];
    const float* Wfc  = (const float*)d_in[2];
    const float* bfc  = (const float*)d_in[3];
    const float* W1   = (const float*)d_in[4];
    const float* al1  = (const float*)d_in[5];
    const float* ar1  = (const float*)d_in[6];
    const float* bias1= (const float*)d_in[7];
    const float* W2   = (const float*)d_in[8];
    const float* al2  = (const float*)d_in[9];
    const float* ar2  = (const float*)d_in[10];
    const float* bias2= (const float*)d_in[11];
    const float* Wih  = (const float*)d_in[12];
    const float* Whh  = (const float*)d_in[13];
    const float* bih  = (const float*)d_in[14];
    const float* bhh  = (const float*)d_in[15];
    const float* gl   = (const float*)d_in[16];
    const float* bl   = (const float*)d_in[17];
    const float* gg   = (const float*)d_in[18];
    const float* bg   = (const float*)d_in[19];
    const float* Wd   = (const float*)d_in[20];
    const float* bd   = (const float*)d_in[21];
    float* out = (float*)d_out;

    int E = in_sizes[1] / 2;

    k_wcomb<<<1, 256>>>(Wfc, bfc, Wih, bih, bhh, Whh);
    k_gatA<<<128, 256>>>(x, Wfc, bfc, W1, al1, ar1);
    k_lstm<<<MROWS / 8, 256>>>(x);
    k_gatB<<<128, 512>>>(ei, E, bias1, W2, al2, ar2, gl, bl, gg, bg, Wd, bd, out, 0);
    k_gatB<<<128, 512>>>(ei, E, bias2, W2, al2, ar2, gl, bl, gg, bg, Wd, bd, out, 1);
}

// round 4
// speedup vs baseline: 1.8113x; 1.2673x over previous
#include <cuda_runtime.h>
#include <math.h>

#define NT 24
#define NPRED 12

// ---- scratch (static device globals; no allocation) ----
__device__ float d_h1[2048 * 64], d_el1[2048], d_er1[2048];
__device__ float d_h2[2048 * 64], d_el2[2048], d_er2[2048];
__device__ float d_lh[2048 * 64];
__device__ unsigned long long d_WhhP[32 * 256];   // packed pairs [kpair][j]
__device__ unsigned long long d_WcombP[4 * 256];  // packed pairs [fpair][j]
__device__ float d_bcomb[256];
__device__ unsigned d_mask[512 * 16];

__device__ __forceinline__ float sigf(float x) {
    return __fdividef(1.0f, 1.0f + __expf(-x));
}
__device__ __forceinline__ float tanh_f(float x) {
    return 2.0f * sigf(2.0f * x) - 1.0f;
}
__device__ __forceinline__ unsigned long long pack2(float a, float b) {
    unsigned long long r;
    asm("mov.b64 %0, {%1,%2};" : "=l"(r) : "f"(a), "f"(b));
    return r;
}
__device__ __forceinline__ void unpack2(unsigned long long v, float& a, float& b) {
    asm("mov.b64 {%0,%1}, %2;" : "=f"(a), "=f"(b) : "l"(v));
}
__device__ __forceinline__ void fma2(unsigned long long& d, unsigned long long a,
                                     unsigned long long b) {
    asm("fma.rn.f32x2 %0, %1, %2, %0;" : "+l"(d) : "l"(a), "l"(b));
}

// ============ k_pre: blocks 0-127 gatA | block 128 wcomb | block 129 mask ============
__global__ void __launch_bounds__(256) k_pre(
    const float* __restrict__ x, const float* __restrict__ Wfc,
    const float* __restrict__ bfc, const float* __restrict__ W1,
    const float* __restrict__ al, const float* __restrict__ ar,
    const float* __restrict__ Wih, const float* __restrict__ bih,
    const float* __restrict__ bhh, const float* __restrict__ Whh,
    const int* __restrict__ ei, int E) {
    int bid = blockIdx.x;
    int tid = threadIdx.x;

    if (bid == 128) {
        // --- wcomb: Wcomb = W_fc @ W_ih^T (packed), bcomb, Whh packed ---
        int j = tid;
        float wih[64];
        const float4* wr = (const float4*)(Wih + j * 64);
#pragma unroll
        for (int q = 0; q < 16; q++) {
            float4 t = wr[q];
            wih[q * 4] = t.x; wih[q * 4 + 1] = t.y;
            wih[q * 4 + 2] = t.z; wih[q * 4 + 3] = t.w;
        }
        float wc[8];
#pragma unroll
        for (int f = 0; f < 8; f++) wc[f] = 0.0f;
        float bj = bih[j] + bhh[j];
#pragma unroll
        for (int h = 0; h < 64; h++) {
            float ww = wih[h];
            bj += bfc[h] * ww;
#pragma unroll
            for (int f = 0; f < 8; f++) wc[f] += Wfc[f * 64 + h] * ww;
        }
#pragma unroll
        for (int fp = 0; fp < 4; fp++)
            d_WcombP[fp * 256 + j] = pack2(wc[2 * fp], wc[2 * fp + 1]);
        d_bcomb[j] = bj;
        const float4* hr = (const float4*)(Whh + j * 64);
#pragma unroll
        for (int q = 0; q < 16; q++) {
            float4 t = hr[q];
            d_WhhP[(2 * q) * 256 + j] = pack2(t.x, t.y);
            d_WhhP[(2 * q + 1) * 256 + j] = pack2(t.z, t.w);
        }
        return;
    }
    if (bid == 129) {
        // --- mask build (global, once) ---
        for (int q = tid; q < 512 * 16; q += 256) d_mask[q] = 0u;
        __syncthreads();
        for (int e = tid; e < E; e += 256) {
            int s = ei[e], t = ei[E + e];
            atomicOr(&d_mask[s * 16 + (t >> 5)], 1u << (t & 31));
        }
        return;
    }

    // --- gatA: 16 nodes/block ---
    __shared__ float Ws[4096];
    __shared__ float wfs[512];
    __shared__ float bfs[64];
    __shared__ float in_s[16 * 64];
    __shared__ float xs[16 * 8];
    __shared__ float red[8][4][2];
    int bn0 = bid * 16;
    {
        const float4* src = (const float4*)W1;
        float4* dst = (float4*)Ws;
        for (int q = tid; q < 1024; q += 256) dst[q] = src[q];
        const float4* s2 = (const float4*)Wfc;
        float4* d2 = (float4*)wfs;
        if (tid < 128) d2[tid] = s2[tid];
    }
    if (tid < 64) bfs[tid] = bfc[tid];
    if (tid < 128) xs[tid] = x[(bn0 + (tid >> 3)) * (NT * 8) + (NT - 1) * 8 + (tid & 7)];
    __syncthreads();
    for (int idx = tid; idx < 1024; idx += 256) {
        int nd = idx >> 6, ii = idx & 63;
        float v = bfs[ii];
#pragma unroll
        for (int f = 0; f < 8; f++) v += xs[nd * 8 + f] * wfs[f * 64 + ii];
        in_s[idx] = v;
    }
    __syncthreads();
    int i = tid & 63, grp = tid >> 6;
    float wcol[64];
#pragma unroll
    for (int k = 0; k < 64; k++) wcol[k] = Ws[k * 64 + i];
    float a_l = al[i], a_r = ar[i];
    float pl[4], pr[4];
#pragma unroll
    for (int q = 0; q < 4; q++) {
        int nd = grp * 4 + q;
        float h = 0.0f;
#pragma unroll
        for (int k = 0; k < 64; k++) h += in_s[nd * 64 + k] * wcol[k];
        d_h1[(size_t)(bn0 + nd) * 64 + i] = h;
        pl[q] = h * a_l; pr[q] = h * a_r;
    }
#pragma unroll
    for (int q = 0; q < 4; q++) {
#pragma unroll
        for (int o = 16; o; o >>= 1) {
            pl[q] += __shfl_xor_sync(~0u, pl[q], o);
            pr[q] += __shfl_xor_sync(~0u, pr[q], o);
        }
    }
    int wp = tid >> 5, lane = tid & 31;
    if (lane == 0) {
#pragma unroll
        for (int q = 0; q < 4; q++) { red[wp][q][0] = pl[q]; red[wp][q][1] = pr[q]; }
    }
    __syncthreads();
    if (tid < 32) {
        int nd = tid >> 1, v = tid & 1;
        int g = nd >> 2, q = nd & 3;
        float s = red[2 * g][q][v] + red[2 * g + 1][q][v];
        if (v) d_er1[bn0 + nd] = s;
        else d_el1[bn0 + nd] = s;
    }
}

// ============ shared GAT core: softmax (no-max) + aggregate + gelu into gs ============
// block handles 8 target nodes m0..m0+7 of batch b. 256 threads.
__device__ __forceinline__ void gat_core(
    int base, int m0, const float* __restrict__ hsrc, const float* __restrict__ elv,
    const float* __restrict__ erv, const float* __restrict__ bias,
    float* p_s, float* er_s, float* gs, unsigned* mask_s,
    float* el_s, float* inv_s, float* sred) {
    int tid = threadIdx.x;
    for (int q = tid; q < 512; q += 256) er_s[q] = erv[base + q];
    if (tid < 8) el_s[tid] = elv[base + m0 + tid];
    if (tid < 128) mask_s[tid] = d_mask[(m0 + (tid >> 4)) * 16 + (tid & 15)];
    __syncthreads();

    // single-pass softmax numerator: p[n][m] = exp(leaky(el[m]+er[n])) masked
    int m = tid & 7, ngrp = tid >> 3;
    {
        float elm = el_s[m];
        unsigned mw = mask_s[m * 16 + (ngrp >> 1)];
        int shb = (ngrp & 1) * 16;
        int nb = ngrp * 16;
        float s = 0.0f;
#pragma unroll
        for (int k = 0; k < 16; k++) {
            int n = nb + k;
            float e = elm + er_s[n];
            e = (e >= 0.0f) ? e : 0.2f * e;
            float pe = ((mw >> (shb + k)) & 1u) ? __expf(e) : 0.0f;
            p_s[n * 8 + m] = pe;
            s += pe;
        }
        s += __shfl_xor_sync(~0u, s, 8);
        s += __shfl_xor_sync(~0u, s, 16);
        int lane = tid & 31, w = tid >> 5;
        if (lane < 8) sred[w * 8 + lane] = s;
    }
    __syncthreads();
    if (tid < 8) {
        float s = 0.0f;
#pragma unroll
        for (int q = 0; q < 8; q++) s += sred[q * 8 + tid];
        inv_s[tid] = __fdividef(1.0f, s);
    }
    __syncthreads();

    // aggregate: thread (i-pair = 2*(tid&31), chunk = tid>>5 of 8 x 64n)
    const float* hb = hsrc + (size_t)base * 64;
    int i2 = (tid & 31) * 2, ch = tid >> 5;
    unsigned long long acc[8];
#pragma unroll
    for (int q = 0; q < 8; q++) acc[q] = 0ull;
    {
        int n0 = ch * 64;
#pragma unroll 8
        for (int nn = 0; nn < 64; nn++) {
            int n = n0 + nn;
            float2 hv = *(const float2*)&hb[(size_t)n * 64 + i2];
            unsigned long long hd0 = pack2(hv.x, hv.x);
            unsigned long long hd1 = pack2(hv.y, hv.y);
            const ulonglong2* pp = (const ulonglong2*)&p_s[n * 8];
            ulonglong2 pa = pp[0], pb = pp[1];
            fma2(acc[0], pa.x, hd0); fma2(acc[1], pa.x, hd1);
            fma2(acc[2], pa.y, hd0); fma2(acc[3], pa.y, hd1);
            fma2(acc[4], pb.x, hd0); fma2(acc[5], pb.x, hd1);
            fma2(acc[6], pb.y, hd0); fma2(acc[7], pb.y, hd1);
        }
    }
    __syncthreads();
    // parts overlay p_s: parts[ch][m][i], 8*8*64 = 4096
#pragma unroll
    for (int q = 0; q < 4; q++) {
#pragma unroll
        for (int qq = 0; qq < 2; qq++) {
            float a, bv;
            unpack2(acc[q * 2 + qq], a, bv);
            p_s[ch * 512 + (2 * q) * 64 + i2 + qq] = a;
            p_s[ch * 512 + (2 * q + 1) * 64 + i2 + qq] = bv;
        }
    }
    __syncthreads();
    for (int oo = tid; oo < 512; oo += 256) {
        float v = 0.0f;
#pragma unroll
        for (int q = 0; q < 8; q++) v += p_s[q * 512 + oo];
        v = v * inv_s[oo >> 6] + bias[oo & 63];
        gs[oo] = 0.5f * v * (1.0f + erff(v * 0.70710678118654752f));
    }
    __syncthreads();
}

// ============ k_main: blocks 0-255 LSTM | blocks 256-511 gatB layer 0 ============
__global__ void __launch_bounds__(256, 2) k_main(
    const float* __restrict__ x, const float* __restrict__ bias1,
    const float* __restrict__ W2, const float* __restrict__ al2,
    const float* __restrict__ ar2) {
    __shared__ __align__(16) float buf[5120];
    __shared__ unsigned mask_s[128];
    __shared__ float el_s[8], inv_s[8], sred[64];
    __shared__ float redE[8][4];
    int tid = threadIdx.x;

    if (blockIdx.x < 256) {
        // ---- LSTM: 8 rows/block ----
        int row0 = blockIdx.x * 8;
        float* xs_all = buf;          // 1536
        float* h_s = buf + 1536;      // 512
        float* gates = buf + 2048;    // 2048
        {
            const float4* src = (const float4*)(x + (size_t)row0 * 192);
            float4* dst = (float4*)xs_all;
            for (int q = tid; q < 384; q += 256) dst[q] = src[q];
        }
        for (int q = tid; q < 512; q += 256) h_s[q] = 0.0f;
        unsigned long long wd[32];
#pragma unroll
        for (int kk = 0; kk < 32; kk++) wd[kk] = d_WhhP[kk * 256 + tid];
        unsigned long long wcd[4];
#pragma unroll
        for (int fp = 0; fp < 4; fp++) wcd[fp] = d_WcombP[fp * 256 + tid];
        float bj = d_bcomb[tid];
        float c0 = 0.0f, c1 = 0.0f;
        __syncthreads();

        for (int t = 0; t < NT; t++) {
            unsigned long long acc[8];
#pragma unroll
            for (int r = 0; r < 8; r++) acc[r] = pack2(bj, 0.0f);
#pragma unroll
            for (int r = 0; r < 8; r++) {
                const unsigned long long* xp =
                    (const unsigned long long*)&xs_all[r * 192 + t * 8];
#pragma unroll
                for (int fp = 0; fp < 4; fp++) fma2(acc[r], xp[fp], wcd[fp]);
            }
#pragma unroll
            for (int k4 = 0; k4 < 16; k4++) {
#pragma unroll
                for (int r = 0; r < 8; r++) {
                    ulonglong2 hv = *(const ulonglong2*)&h_s[r * 64 + k4 * 4];
                    fma2(acc[r], hv.x, wd[2 * k4]);
                    fma2(acc[r], hv.y, wd[2 * k4 + 1]);
                }
            }
#pragma unroll
            for (int r = 0; r < 8; r++) {
                float a, bv;
                unpack2(acc[r], a, bv);
                gates[r * 256 + tid] = a + bv;
            }
            __syncthreads();
            {
                int r = tid >> 6, ii = tid & 63;
                float gi = gates[r * 256 + ii];
                float gf = gates[r * 256 + 64 + ii];
                float gG = gates[r * 256 + 128 + ii];
                float go = gates[r * 256 + 192 + ii];
                float c = sigf(gf) * c0 + sigf(gi) * tanh_f(gG);
                c0 = c;
                h_s[r * 64 + ii] = sigf(go) * tanh_f(c);
            }
            {
                int idx = tid + 256;
                int r = idx >> 6, ii = idx & 63;
                float gi = gates[r * 256 + ii];
                float gf = gates[r * 256 + 64 + ii];
                float gG = gates[r * 256 + 128 + ii];
                float go = gates[r * 256 + 192 + ii];
                float c = sigf(gf) * c1 + sigf(gi) * tanh_f(gG);
                c1 = c;
                h_s[r * 64 + ii] = sigf(go) * tanh_f(c);
            }
            __syncthreads();
        }
        for (int q = tid; q < 512; q += 256) d_lh[(size_t)row0 * 64 + q] = h_s[q];
        return;
    }

    // ---- gatB layer 0 + fused layer-2 projection ----
    int bid2 = blockIdx.x - 256;
    int b = bid2 >> 6, m0 = (bid2 & 63) * 8;
    int base = b * 512;
    float* p_s = buf;
    float* er_s = buf + 4096;
    float* gs = buf + 4608;

    gat_core(base, m0, d_h1, d_el1, d_er1, bias1, p_s, er_s, gs, mask_s, el_s, inv_s, sred);

    // fused layer-2 projection: h2 = gs @ W2; el2/er2
    for (int q = tid; q < 4096; q += 256) p_s[q] = W2[q];
    __syncthreads();
    int i = tid & 63, g = tid >> 6;
    float h2a = 0.0f, h2b = 0.0f;
#pragma unroll
    for (int k = 0; k < 64; k++) {
        float wv = p_s[k * 64 + i];
        h2a += gs[g * 64 + k] * wv;
        h2b += gs[(g + 4) * 64 + k] * wv;
    }
    d_h2[(size_t)(base + m0 + g) * 64 + i] = h2a;
    d_h2[(size_t)(base + m0 + g + 4) * 64 + i] = h2b;
    float a_l = al2[i], a_r = ar2[i];
    float pla = h2a * a_l, pra = h2a * a_r, plb = h2b * a_l, prb = h2b * a_r;
#pragma unroll
    for (int o = 16; o; o >>= 1) {
        pla += __shfl_xor_sync(~0u, pla, o);
        pra += __shfl_xor_sync(~0u, pra, o);
        plb += __shfl_xor_sync(~0u, plb, o);
        prb += __shfl_xor_sync(~0u, prb, o);
    }
    int lane = tid & 31, w = tid >> 5;
    if (lane == 0) { redE[w][0] = pla; redE[w][1] = pra; redE[w][2] = plb; redE[w][3] = prb; }
    __syncthreads();
    if (tid < 16) {
        int mm = tid >> 1, v = tid & 1;
        int g2 = mm & 3, hi = mm >> 2;
        float s = redE[2 * g2][hi * 2 + v] + redE[2 * g2 + 1][hi * 2 + v];
        if (v) d_er2[base + m0 + mm] = s;
        else d_el2[base + m0 + mm] = s;
    }
}

// ============ k_last: gatB layer 1 + fused LN + decode ============
__global__ void __launch_bounds__(256) k_last(
    const float* __restrict__ bias2, const float* __restrict__ gl,
    const float* __restrict__ bl, const float* __restrict__ gg,
    const float* __restrict__ bg, const float* __restrict__ Wd,
    const float* __restrict__ bd, float* __restrict__ out) {
    __shared__ __align__(16) float buf[5120];
    __shared__ unsigned mask_s[128];
    __shared__ float el_s[8], inv_s[8], sred[64];
    int tid = threadIdx.x;
    int b = blockIdx.x >> 6, m0 = (blockIdx.x & 63) * 8;
    int base = b * 512;
    float* p_s = buf;
    float* er_s = buf + 4096;
    float* gs = buf + 4608;

    gat_core(base, m0, d_h2, d_el2, d_er2, bias2, p_s, er_s, gs, mask_s, el_s, inv_s, sred);

    // fused final: dual layernorm + add + decode; warp w -> node m0+w
    float* lh_s = p_s;        // 512
    float* Wds = p_s + 512;   // 768
    for (int q = tid; q < 512; q += 256) lh_s[q] = d_lh[(size_t)(base + m0) * 64 + q];
    for (int q = tid; q < 768; q += 256) Wds[q] = Wd[q];
    __syncthreads();
    int lane = tid & 31, w = tid >> 5;
    int ia = lane, ib = lane + 32;
    float vg0 = gs[w * 64 + ia], vg1 = gs[w * 64 + ib];
    float vl0 = lh_s[w * 64 + ia], vl1 = lh_s[w * 64 + ib];
    float s1 = vg0 + vg1, s2 = vg0 * vg0 + vg1 * vg1;
    float s3 = vl0 + vl1, s4 = vl0 * vl0 + vl1 * vl1;
#pragma unroll
    for (int o = 16; o; o >>= 1) {
        s1 += __shfl_xor_sync(~0u, s1, o);
        s2 += __shfl_xor_sync(~0u, s2, o);
        s3 += __shfl_xor_sync(~0u, s3, o);
        s4 += __shfl_xor_sync(~0u, s4, o);
    }
    const float invH = 1.0f / 64.0f;
    float mug = s1 * invH, varg = s2 * invH - mug * mug;
    float mul_ = s3 * invH, varl = s4 * invH - mul_ * mul_;
    float rg = rsqrtf(varg + 1e-5f), rl = rsqrtf(varl + 1e-5f);
    float h0 = (vg0 - mug) * rg * gg[ia] + bg[ia] + (vl0 - mul_) * rl * gl[ia] + bl[ia];
    float h1v = (vg1 - mug) * rg * gg[ib] + bg[ib] + (vl1 - mul_) * rl * gl[ib] + bl[ib];
    __syncwarp();
    lh_s[w * 64 + ia] = h0;
    lh_s[w * 64 + ib] = h1v;
    __syncwarp();
    if (lane < NPRED) {
        float o = bd[lane];
#pragma unroll
        for (int k = 0; k < 64; k++) o += lh_s[w * 64 + k] * Wds[k * NPRED + lane];
        out[(size_t)(base + m0 + w) * NPRED + lane] = o;
    }
}

extern "C" void kernel_launch(void* const* d_in, const int* in_sizes, int n_in,
                              void* d_out, int out_size) {
    const float* x    = (const float*)d_in[0];
    const int*   ei   = (const int*)d_in[1];
    const float* Wfc  = (const float*)d_in[2];
    const float* bfc  = (const float*)d_in[3];
    const float* W1   = (const float*)d_in[4];
    const float* al1  = (const float*)d_in[5];
    const float* ar1  = (const float*)d_in[6];
    const float* bias1= (const float*)d_in[7];
    const float* W2   = (const float*)d_in[8];
    const float* al2  = (const float*)d_in[9];
    const float* ar2  = (const float*)d_in[10];
    const float* bias2= (const float*)d_in[11];
    const float* Wih  = (const float*)d_in[12];
    const float* Whh  = (const float*)d_in[13];
    const float* bih  = (const float*)d_in[14];
    const float* bhh  = (const float*)d_in[15];
    const float* gl   = (const float*)d_in[16];
    const float* bl   = (const float*)d_in[17];
    const float* gg   = (const float*)d_in[18];
    const float* bg   = (const float*)d_in[19];
    const float* Wd   = (const float*)d_in[20];
    const float* bd   = (const float*)d_in[21];
    float* out = (float*)d_out;

    int E = in_sizes[1] / 2;

    k_pre<<<130, 256>>>(x, Wfc, bfc, W1, al1, ar1, Wih, bih, bhh, Whh, ei, E);
    k_main<<<512, 256>>>(x, bias1, W2, al2, ar2);
    k_last<<<256, 256>>>(bias2, gl, bl, gg, bg, Wd, bd, out);
}

// round 5
// speedup vs baseline: 1.8170x; 1.0032x over previous
#include <cuda_runtime.h>
#include <math.h>

#define NT 24
#define NPRED 12

// ---- scratch (static device globals; no allocation) ----
__device__ float d_h1[2048 * 64], d_el1[2048], d_er1[2048];
__device__ float d_h2[2048 * 64], d_el2[2048], d_er2[2048];
__device__ float d_lh[2048 * 64];
__device__ unsigned long long d_WhhP[32 * 256];   // packed pairs [kpair][j]
__device__ unsigned long long d_WcombP[4 * 256];  // packed pairs [fpair][j]
__device__ float d_bcomb[256];
__device__ unsigned d_mask[512 * 16];

__device__ __forceinline__ float sigf(float x) {
    return __fdividef(1.0f, 1.0f + __expf(-x));
}
__device__ __forceinline__ float tanh_f(float x) {
    return 2.0f * sigf(2.0f * x) - 1.0f;
}
__device__ __forceinline__ unsigned long long pack2(float a, float b) {
    unsigned long long r;
    asm("mov.b64 %0, {%1,%2};" : "=l"(r) : "f"(a), "f"(b));
    return r;
}
__device__ __forceinline__ void unpack2(unsigned long long v, float& a, float& b) {
    asm("mov.b64 {%0,%1}, %2;" : "=f"(a), "=f"(b) : "l"(v));
}
__device__ __forceinline__ void fma2(unsigned long long& d, unsigned long long a,
                                     unsigned long long b) {
    asm("fma.rn.f32x2 %0, %1, %2, %0;" : "+l"(d) : "l"(a), "l"(b));
}

// ============ k_zero: clear mask (parallel) ============
__global__ void k_zero() {
    d_mask[blockIdx.x * 256 + threadIdx.x] = 0u;
}

// ============ k_pre: 0-127 gatA | 128-135 wcomb | 136-171 mask set ============
__global__ void __launch_bounds__(256) k_pre(
    const float* __restrict__ x, const float* __restrict__ Wfc,
    const float* __restrict__ bfc, const float* __restrict__ W1,
    const float* __restrict__ al, const float* __restrict__ ar,
    const float* __restrict__ Wih, const float* __restrict__ bih,
    const float* __restrict__ bhh, const float* __restrict__ Whh,
    const int* __restrict__ ei, int E) {
    int bid = blockIdx.x;
    int tid = threadIdx.x;

    if (bid >= 136) {
        // --- mask set: 256 edges per block, one latency round ---
        int e = (bid - 136) * 256 + tid;
        if (e < E) {
            int s = ei[e], t = ei[E + e];
            atomicOr(&d_mask[s * 16 + (t >> 5)], 1u << (t & 31));
        }
        return;
    }
    if (bid >= 128) {
        // --- wcomb: 32 gate-rows per block, coalesced staging ---
        int jb = (bid - 128) * 32;
        __shared__ float wih_s[32 * 64];
        __shared__ float whh_s[32 * 64];
        __shared__ float wc_s[32 * 8];
        {
            const float4* s1 = (const float4*)(Wih + jb * 64);
            const float4* s2 = (const float4*)(Whh + jb * 64);
            float4* t1 = (float4*)wih_s;
            float4* t2 = (float4*)whh_s;
            for (int q = tid; q < 512; q += 256) { t1[q] = s1[q]; t2[q] = s2[q]; }
        }
        __syncthreads();
        {
            int jl = tid >> 3, f = tid & 7;
            float s = 0.0f;
#pragma unroll
            for (int h = 0; h < 64; h++) s += Wfc[f * 64 + h] * wih_s[jl * 64 + h];
            wc_s[jl * 8 + f] = s;
            if (f == 0) {
                int j = jb + jl;
                float bj = bih[j] + bhh[j];
#pragma unroll
                for (int h = 0; h < 64; h++) bj += bfc[h] * wih_s[jl * 64 + h];
                d_bcomb[j] = bj;
            }
        }
        __syncthreads();
        {
            // pack Wcomb: 32 j x 4 fpairs = 128 entries
            if (tid < 128) {
                int jl = tid & 31, fp = tid >> 5;
                d_WcombP[fp * 256 + jb + jl] =
                    pack2(wc_s[jl * 8 + 2 * fp], wc_s[jl * 8 + 2 * fp + 1]);
            }
            // pack Whh: 32 j x 32 kpairs = 1024 entries, 4 per thread
#pragma unroll
            for (int q = 0; q < 4; q++) {
                int idx = tid + q * 256;
                int jl = idx & 31, k2 = idx >> 5;
                d_WhhP[k2 * 256 + jb + jl] =
                    pack2(whh_s[jl * 64 + 2 * k2], whh_s[jl * 64 + 2 * k2 + 1]);
            }
        }
        return;
    }

    // --- gatA: 16 nodes/block ---
    __shared__ float Ws[4096];
    __shared__ float wfs[512];
    __shared__ float bfs[64];
    __shared__ float in_s[16 * 64];
    __shared__ float xs[16 * 8];
    __shared__ float red[8][4][2];
    int bn0 = bid * 16;
    {
        const float4* src = (const float4*)W1;
        float4* dst = (float4*)Ws;
        for (int q = tid; q < 1024; q += 256) dst[q] = src[q];
        const float4* s2 = (const float4*)Wfc;
        float4* d2 = (float4*)wfs;
        if (tid < 128) d2[tid] = s2[tid];
    }
    if (tid < 64) bfs[tid] = bfc[tid];
    if (tid < 128) xs[tid] = x[(bn0 + (tid >> 3)) * (NT * 8) + (NT - 1) * 8 + (tid & 7)];
    __syncthreads();
    for (int idx = tid; idx < 1024; idx += 256) {
        int nd = idx >> 6, ii = idx & 63;
        float v = bfs[ii];
#pragma unroll
        for (int f = 0; f < 8; f++) v += xs[nd * 8 + f] * wfs[f * 64 + ii];
        in_s[idx] = v;
    }
    __syncthreads();
    int i = tid & 63, grp = tid >> 6;
    float wcol[64];
#pragma unroll
    for (int k = 0; k < 64; k++) wcol[k] = Ws[k * 64 + i];
    float a_l = al[i], a_r = ar[i];
    float pl[4], pr[4];
#pragma unroll
    for (int q = 0; q < 4; q++) {
        int nd = grp * 4 + q;
        float h = 0.0f;
#pragma unroll
        for (int k = 0; k < 64; k++) h += in_s[nd * 64 + k] * wcol[k];
        d_h1[(size_t)(bn0 + nd) * 64 + i] = h;
        pl[q] = h * a_l; pr[q] = h * a_r;
    }
#pragma unroll
    for (int q = 0; q < 4; q++) {
#pragma unroll
        for (int o = 16; o; o >>= 1) {
            pl[q] += __shfl_xor_sync(~0u, pl[q], o);
            pr[q] += __shfl_xor_sync(~0u, pr[q], o);
        }
    }
    int wp = tid >> 5, lane = tid & 31;
    if (lane == 0) {
#pragma unroll
        for (int q = 0; q < 4; q++) { red[wp][q][0] = pl[q]; red[wp][q][1] = pr[q]; }
    }
    __syncthreads();
    if (tid < 32) {
        int nd = tid >> 1, v = tid & 1;
        int g = nd >> 2, q = nd & 3;
        float s = red[2 * g][q][v] + red[2 * g + 1][q][v];
        if (v) d_er1[bn0 + nd] = s;
        else d_el1[bn0 + nd] = s;
    }
}

// ============ shared GAT core (8 targets/block, 256 threads) ============
__device__ __forceinline__ void gat_core(
    int base, int m0, const float* __restrict__ hsrc, const float* __restrict__ elv,
    const float* __restrict__ erv, const float* __restrict__ bias,
    float* p_s, float* er_s, float* gs, unsigned* mask_s,
    float* el_s, float* inv_s, float* sred) {
    int tid = threadIdx.x;
    for (int q = tid; q < 512; q += 256) er_s[q] = erv[base + q];
    if (tid < 8) el_s[tid] = elv[base + m0 + tid];
    if (tid < 128) mask_s[tid] = d_mask[(m0 + (tid >> 4)) * 16 + (tid & 15)];
    __syncthreads();

    int m = tid & 7, ngrp = tid >> 3;
    {
        float elm = el_s[m];
        unsigned mw = mask_s[m * 16 + (ngrp >> 1)];
        int shb = (ngrp & 1) * 16;
        int nb = ngrp * 16;
        float s = 0.0f;
#pragma unroll
        for (int k = 0; k < 16; k++) {
            int n = nb + k;
            float e = elm + er_s[n];
            e = (e >= 0.0f) ? e : 0.2f * e;
            float pe = ((mw >> (shb + k)) & 1u) ? __expf(e) : 0.0f;
            p_s[n * 8 + m] = pe;
            s += pe;
        }
        s += __shfl_xor_sync(~0u, s, 8);
        s += __shfl_xor_sync(~0u, s, 16);
        int lane = tid & 31, w = tid >> 5;
        if (lane < 8) sred[w * 8 + lane] = s;
    }
    __syncthreads();
    if (tid < 8) {
        float s = 0.0f;
#pragma unroll
        for (int q = 0; q < 8; q++) s += sred[q * 8 + tid];
        inv_s[tid] = __fdividef(1.0f, s);
    }
    __syncthreads();

    const float* hb = hsrc + (size_t)base * 64;
    int i2 = (tid & 31) * 2, ch = tid >> 5;
    unsigned long long acc[8];
#pragma unroll
    for (int q = 0; q < 8; q++) acc[q] = 0ull;
    {
        int n0 = ch * 64;
#pragma unroll 8
        for (int nn = 0; nn < 64; nn++) {
            int n = n0 + nn;
            float2 hv = *(const float2*)&hb[(size_t)n * 64 + i2];
            unsigned long long hd0 = pack2(hv.x, hv.x);
            unsigned long long hd1 = pack2(hv.y, hv.y);
            const ulonglong2* pp = (const ulonglong2*)&p_s[n * 8];
            ulonglong2 pa = pp[0], pb = pp[1];
            fma2(acc[0], pa.x, hd0); fma2(acc[1], pa.x, hd1);
            fma2(acc[2], pa.y, hd0); fma2(acc[3], pa.y, hd1);
            fma2(acc[4], pb.x, hd0); fma2(acc[5], pb.x, hd1);
            fma2(acc[6], pb.y, hd0); fma2(acc[7], pb.y, hd1);
        }
    }
    __syncthreads();
#pragma unroll
    for (int q = 0; q < 4; q++) {
#pragma unroll
        for (int qq = 0; qq < 2; qq++) {
            float a, bv;
            unpack2(acc[q * 2 + qq], a, bv);
            p_s[ch * 512 + (2 * q) * 64 + i2 + qq] = a;
            p_s[ch * 512 + (2 * q + 1) * 64 + i2 + qq] = bv;
        }
    }
    __syncthreads();
    for (int oo = tid; oo < 512; oo += 256) {
        float v = 0.0f;
#pragma unroll
        for (int q = 0; q < 8; q++) v += p_s[q * 512 + oo];
        v = v * inv_s[oo >> 6] + bias[oo & 63];
        gs[oo] = 0.5f * v * (1.0f + erff(v * 0.70710678118654752f));
    }
    __syncthreads();
}

// ============ k_main: interleaved LSTM | gatB layer 0 ============
// bids 0-147 LSTM(0-147), 148-295 gatB(0-147), 296-403 LSTM(148-255), 404-511 gatB(148-255)
__global__ void __launch_bounds__(256, 2) k_main(
    const float* __restrict__ x, const float* __restrict__ bias1,
    const float* __restrict__ W2, const float* __restrict__ al2,
    const float* __restrict__ ar2) {
    __shared__ __align__(16) float buf[5120];
    __shared__ unsigned mask_s[128];
    __shared__ float el_s[8], inv_s[8], sred[64];
    __shared__ float redE[8][4];
    int tid = threadIdx.x;
    int bid = blockIdx.x;
    int isLstm, widx;
    if (bid < 148) { isLstm = 1; widx = bid; }
    else if (bid < 296) { isLstm = 0; widx = bid - 148; }
    else if (bid < 404) { isLstm = 1; widx = bid - 148; }
    else { isLstm = 0; widx = bid - 256; }

    if (isLstm) {
        // ---- LSTM: 8 rows/block ----
        int row0 = widx * 8;
        float* xs_all = buf;          // 1536
        float* h_s = buf + 1536;      // 512
        float* gates = buf + 2048;    // 2048
        {
            const float4* src = (const float4*)(x + (size_t)row0 * 192);
            float4* dst = (float4*)xs_all;
            for (int q = tid; q < 384; q += 256) dst[q] = src[q];
        }
        for (int q = tid; q < 512; q += 256) h_s[q] = 0.0f;
        unsigned long long wd[32];
#pragma unroll
        for (int kk = 0; kk < 32; kk++) wd[kk] = d_WhhP[kk * 256 + tid];
        unsigned long long wcd[4];
#pragma unroll
        for (int fp = 0; fp < 4; fp++) wcd[fp] = d_WcombP[fp * 256 + tid];
        float bj = d_bcomb[tid];
        float c0 = 0.0f, c1 = 0.0f;
        __syncthreads();

        for (int t = 0; t < NT; t++) {
            unsigned long long acc[8];
#pragma unroll
            for (int r = 0; r < 8; r++) acc[r] = pack2(bj, 0.0f);
#pragma unroll
            for (int r = 0; r < 8; r++) {
                const unsigned long long* xp =
                    (const unsigned long long*)&xs_all[r * 192 + t * 8];
#pragma unroll
                for (int fp = 0; fp < 4; fp++) fma2(acc[r], xp[fp], wcd[fp]);
            }
#pragma unroll
            for (int k4 = 0; k4 < 16; k4++) {
#pragma unroll
                for (int r = 0; r < 8; r++) {
                    ulonglong2 hv = *(const ulonglong2*)&h_s[r * 64 + k4 * 4];
                    fma2(acc[r], hv.x, wd[2 * k4]);
                    fma2(acc[r], hv.y, wd[2 * k4 + 1]);
                }
            }
#pragma unroll
            for (int r = 0; r < 8; r++) {
                float a, bv;
                unpack2(acc[r], a, bv);
                gates[r * 256 + tid] = a + bv;
            }
            __syncthreads();
            {
                int r = tid >> 6, ii = tid & 63;
                float gi = gates[r * 256 + ii];
                float gf = gates[r * 256 + 64 + ii];
                float gG = gates[r * 256 + 128 + ii];
                float go = gates[r * 256 + 192 + ii];
                float c = sigf(gf) * c0 + sigf(gi) * tanh_f(gG);
                c0 = c;
                h_s[r * 64 + ii] = sigf(go) * tanh_f(c);
            }
            {
                int idx = tid + 256;
                int r = idx >> 6, ii = idx & 63;
                float gi = gates[r * 256 + ii];
                float gf = gates[r * 256 + 64 + ii];
                float gG = gates[r * 256 + 128 + ii];
                float go = gates[r * 256 + 192 + ii];
                float c = sigf(gf) * c1 + sigf(gi) * tanh_f(gG);
                c1 = c;
                h_s[r * 64 + ii] = sigf(go) * tanh_f(c);
            }
            __syncthreads();
        }
        for (int q = tid; q < 512; q += 256) d_lh[(size_t)row0 * 64 + q] = h_s[q];
        return;
    }

    // ---- gatB layer 0 + fused layer-2 projection ----
    int b = widx >> 6, m0 = (widx & 63) * 8;
    int base = b * 512;
    float* p_s = buf;
    float* er_s = buf + 4096;
    float* gs = buf + 4608;

    gat_core(base, m0, d_h1, d_el1, d_er1, bias1, p_s, er_s, gs, mask_s, el_s, inv_s, sred);

    for (int q = tid; q < 4096; q += 256) p_s[q] = W2[q];
    __syncthreads();
    int i = tid & 63, g = tid >> 6;
    float h2a = 0.0f, h2b = 0.0f;
#pragma unroll
    for (int k = 0; k < 64; k++) {
        float wv = p_s[k * 64 + i];
        h2a += gs[g * 64 + k] * wv;
        h2b += gs[(g + 4) * 64 + k] * wv;
    }
    d_h2[(size_t)(base + m0 + g) * 64 + i] = h2a;
    d_h2[(size_t)(base + m0 + g + 4) * 64 + i] = h2b;
    float a_l = al2[i], a_r = ar2[i];
    float pla = h2a * a_l, pra = h2a * a_r, plb = h2b * a_l, prb = h2b * a_r;
#pragma unroll
    for (int o = 16; o; o >>= 1) {
        pla += __shfl_xor_sync(~0u, pla, o);
        pra += __shfl_xor_sync(~0u, pra, o);
        plb += __shfl_xor_sync(~0u, plb, o);
        prb += __shfl_xor_sync(~0u, prb, o);
    }
    int lane = tid & 31, w = tid >> 5;
    if (lane == 0) { redE[w][0] = pla; redE[w][1] = pra; redE[w][2] = plb; redE[w][3] = prb; }
    __syncthreads();
    if (tid < 16) {
        int mm = tid >> 1, v = tid & 1;
        int g2 = mm & 3, hi = mm >> 2;
        float s = redE[2 * g2][hi * 2 + v] + redE[2 * g2 + 1][hi * 2 + v];
        if (v) d_er2[base + m0 + mm] = s;
        else d_el2[base + m0 + mm] = s;
    }
}

// ============ k_last: gatB layer 1 + fused LN + decode ============
__global__ void __launch_bounds__(256) k_last(
    const float* __restrict__ bias2, const float* __restrict__ gl,
    const float* __restrict__ bl, const float* __restrict__ gg,
    const float* __restrict__ bg, const float* __restrict__ Wd,
    const float* __restrict__ bd, float* __restrict__ out) {
    __shared__ __align__(16) float buf[5120];
    __shared__ unsigned mask_s[128];
    __shared__ float el_s[8], inv_s[8], sred[64];
    int tid = threadIdx.x;
    int b = blockIdx.x >> 6, m0 = (blockIdx.x & 63) * 8;
    int base = b * 512;
    float* p_s = buf;
    float* er_s = buf + 4096;
    float* gs = buf + 4608;

    gat_core(base, m0, d_h2, d_el2, d_er2, bias2, p_s, er_s, gs, mask_s, el_s, inv_s, sred);

    float* lh_s = p_s;
    float* Wds = p_s + 512;
    for (int q = tid; q < 512; q += 256) lh_s[q] = d_lh[(size_t)(base + m0) * 64 + q];
    for (int q = tid; q < 768; q += 256) Wds[q] = Wd[q];
    __syncthreads();
    int lane = tid & 31, w = tid >> 5;
    int ia = lane, ib = lane + 32;
    float vg0 = gs[w * 64 + ia], vg1 = gs[w * 64 + ib];
    float vl0 = lh_s[w * 64 + ia], vl1 = lh_s[w * 64 + ib];
    float s1 = vg0 + vg1, s2 = vg0 * vg0 + vg1 * vg1;
    float s3 = vl0 + vl1, s4 = vl0 * vl0 + vl1 * vl1;
#pragma unroll
    for (int o = 16; o; o >>= 1) {
        s1 += __shfl_xor_sync(~0u, s1, o);
        s2 += __shfl_xor_sync(~0u, s2, o);
        s3 += __shfl_xor_sync(~0u, s3, o);
        s4 += __shfl_xor_sync(~0u, s4, o);
    }
    const float invH = 1.0f / 64.0f;
    float mug = s1 * invH, varg = s2 * invH - mug * mug;
    float mul_ = s3 * invH, varl = s4 * invH - mul_ * mul_;
    float rg = rsqrtf(varg + 1e-5f), rl = rsqrtf(varl + 1e-5f);
    float h0 = (vg0 - mug) * rg * gg[ia] + bg[ia] + (vl0 - mul_) * rl * gl[ia] + bl[ia];
    float h1v = (vg1 - mug) * rg * gg[ib] + bg[ib] + (vl1 - mul_) * rl * gl[ib] + bl[ib];
    __syncwarp();
    lh_s[w * 64 + ia] = h0;
    lh_s[w * 64 + ib] = h1v;
    __syncwarp();
    if (lane < NPRED) {
        float o = bd[lane];
#pragma unroll
        for (int k = 0; k < 64; k++) o += lh_s[w * 64 + k] * Wds[k * NPRED + lane];
        out[(size_t)(base + m0 + w) * NPRED + lane] = o;
    }
}

extern "C" void kernel_launch(void* const* d_in, const int* in_sizes, int n_in,
                              void* d_out, int out_size) {
    const float* x    = (const float*)d_in[0];
    const int*   ei   = (const int*)d_in[1];
    const float* Wfc  = (const float*)d_in[2];
    const float* bfc  = (const float*)d_in[3];
    const float* W1   = (const float*)d_in[4];
    const float* al1  = (const float*)d_in[5];
    const float* ar1  = (const float*)d_in[6];
    const float* bias1= (const float*)d_in[7];
    const float* W2   = (const float*)d_in[8];
    const float* al2  = (const float*)d_in[9];
    const float* ar2  = (const float*)d_in[10];
    const float* bias2= (const float*)d_in[11];
    const float* Wih  = (const float*)d_in[12];
    const float* Whh  = (const float*)d_in[13];
    const float* bih  = (const float*)d_in[14];
    const float* bhh  = (const float*)d_in[15];
    const float* gl   = (const float*)d_in[16];
    const float* bl   = (const float*)d_in[17];
    const float* gg   = (const float*)d_in[18];
    const float* bg   = (const float*)d_in[19];
    const float* Wd   = (const float*)d_in[20];
    const float* bd   = (const float*)d_in[21];
    float* out = (float*)d_out;

    int E = in_sizes[1] / 2;
    int maskBlocks = (E + 255) / 256;

    k_zero<<<32, 256>>>();
    k_pre<<<136 + maskBlocks, 256>>>(x, Wfc, bfc, W1, al1, ar1, Wih, bih, bhh, Whh, ei, E);
    k_main<<<512, 256>>>(x, bias1, W2, al2, ar2);
    k_last<<<256, 256>>>(bias2, gl, bl, gg, bg, Wd, bd, out);
}